// round 4
// baseline (speedup 1.0000x reference)
#include <cuda_runtime.h>
#include <cuda_bf16.h>

#define BB 16
#define FF 32
#define CC 32
#define NN 200
#define TT 48
#define SS 3
#define NT 8
#define MT 5
#define NCHUNK (NN / MT)       // 40
#define NTFLAT (NN * TT)       // 9600

typedef unsigned long long u64;

// ---- f32x2 helpers (Blackwell packed fp32) ----
__device__ __forceinline__ u64 ffma2(u64 a, u64 b, u64 c) {
    u64 d;
    asm("fma.rn.f32x2 %0, %1, %2, %3;" : "=l"(d) : "l"(a), "l"(b), "l"(c));
    return d;
}
__device__ __forceinline__ float2 unpack2(u64 v) {
    float2 r;
    asm("mov.b64 {%0, %1}, %2;" : "=f"(r.x), "=f"(r.y) : "l"(v));
    return r;
}

// Scratch (device globals)
__device__ float g_wh[SS][BB][NTFLAT * CC];   // [(n,t)][c]
__device__ float g_f1[SS][BB][NTFLAT];
__device__ float g_f2[SS][BB][NTFLAT];
__device__ float g_f2max[SS][BB][TT];
__device__ float g_y[6][BB][NTFLAT * CC];     // slot = 2*s + hop

// ---------------------------------------------------------------------------
// Wh + f1/f2. GEMM M=9600 x K=32 x N=32 per (s,b). grid (75, BB, SS), 256 thr.
// ---------------------------------------------------------------------------
__global__ __launch_bounds__(256) void wh_kernel(
    const float* __restrict__ xin,
    const float* __restrict__ Wb,
    const float* __restrict__ ab,
    int layout)
{
    const int b = blockIdx.y, s = blockIdx.z;
    const int base = blockIdx.x * 128;
    const int tid = threadIdx.x;

    __shared__ float xs[128 * 33];
    __shared__ float Ws[FF * CC];
    __shared__ float as_[2 * CC];

    if (layout == 0) {
        const float* src = xin + (size_t)b * FF * NTFLAT + base;
        #pragma unroll
        for (int k = 0; k < 4; k++) {
            int idx4 = tid + 256 * k;
            int f = idx4 >> 5, r4 = (idx4 & 31) * 4;
            float4 v = *(const float4*)(src + (size_t)f * NTFLAT + r4);
            xs[(r4 + 0) * 33 + f] = v.x;
            xs[(r4 + 1) * 33 + f] = v.y;
            xs[(r4 + 2) * 33 + f] = v.z;
            xs[(r4 + 3) * 33 + f] = v.w;
        }
    } else {
        const float* src = &g_y[2 * s][b][(size_t)base * CC];
        #pragma unroll
        for (int k = 0; k < 4; k++) {
            int idx4 = tid + 256 * k;
            int row = idx4 >> 3, q = (idx4 & 7) * 4;
            float4 v = *(const float4*)(src + idx4 * 4);
            xs[row * 33 + q + 0] = v.x;
            xs[row * 33 + q + 1] = v.y;
            xs[row * 33 + q + 2] = v.z;
            xs[row * 33 + q + 3] = v.w;
        }
    }
    {
        const float* W = Wb + (s * BB + b) * (FF * CC);
        if (tid < 256) ((float4*)Ws)[tid] = ((const float4*)W)[tid];
        if (tid < 2 * CC) as_[tid] = ab[(s * BB + b) * (2 * CC) + tid];
    }
    __syncthreads();

    const int cg = tid & 15, rg = tid >> 4;
    const int r0 = rg * 8;
    float acc[8][2];
    #pragma unroll
    for (int i = 0; i < 8; i++) { acc[i][0] = 0.f; acc[i][1] = 0.f; }

    #pragma unroll 8
    for (int f = 0; f < FF; f++) {
        float2 wv = *(const float2*)&Ws[f * CC + 2 * cg];
        #pragma unroll
        for (int i = 0; i < 8; i++) {
            float xv = xs[(r0 + i) * 33 + f];
            acc[i][0] += xv * wv.x;
            acc[i][1] += xv * wv.y;
        }
    }

    float* whp = &g_wh[s][b][0];
    #pragma unroll
    for (int i = 0; i < 8; i++)
        *(float2*)&whp[(size_t)(base + r0 + i) * CC + 2 * cg] =
            make_float2(acc[i][0], acc[i][1]);

    float a1l = as_[2 * cg], a1h = as_[2 * cg + 1];
    float a2l = as_[CC + 2 * cg], a2h = as_[CC + 2 * cg + 1];
    #pragma unroll
    for (int i = 0; i < 8; i++) {
        float p1 = acc[i][0] * a1l + acc[i][1] * a1h;
        float p2 = acc[i][0] * a2l + acc[i][1] * a2h;
        #pragma unroll
        for (int off = 8; off >= 1; off >>= 1) {
            p1 += __shfl_xor_sync(0xffffffffu, p1, off);
            p2 += __shfl_xor_sync(0xffffffffu, p2, off);
        }
        if (cg == 0) {
            g_f1[s][b][base + r0 + i] = p1;
            g_f2[s][b][base + r0 + i] = p2;
        }
    }
}

// ---------------------------------------------------------------------------
__global__ void f2max_kernel()
{
    const int b = blockIdx.x, s = blockIdx.y, t = threadIdx.x;
    if (t < TT) {
        float m = -1e30f;
        for (int n = 0; n < NN; n++) m = fmaxf(m, g_f2[s][b][n * TT + t]);
        g_f2max[s][b][t] = m;
    }
}

// ---------------------------------------------------------------------------
// Attention-aggregation. R2 structure (synchronous copies, MT=5) with f32x2
// step-2. grid (25, BB, SS), block 256. cg=tid&15 (c-pair), tg=tid>>4 (3 t's).
// ---------------------------------------------------------------------------
__global__ __launch_bounds__(256) void agg_kernel(const int* __restrict__ support, int hop)
{
    const int nt = blockIdx.x, b = blockIdx.y, s = blockIdx.z;
    const int n0 = nt * NT;
    const int tid = threadIdx.x;

    __shared__ __align__(16) float whs[MT * TT * CC];      // [m][t][c]  30720 B
    __shared__ __align__(16) float ws2[MT * TT * NT * 2];  // [m][t][nn*2] dup pairs 15360 B
    __shared__ float f1s[TT * NT];
    __shared__ float mhs[TT * NT];
    __shared__ float zs [TT * NT];
    __shared__ float f2c[MT * TT];
    __shared__ float fms[TT];
    __shared__ float masks[NT * MT];

    if (tid < TT) fms[tid] = g_f2max[s][b][tid];
    __syncthreads();
    for (int idx = tid; idx < TT * NT; idx += 256) {
        int t = idx >> 3, nn = idx & 7;
        float f1v = g_f1[s][b][(n0 + nn) * TT + t];
        f1s[idx] = f1v;
        zs[idx] = 0.f;
        float sv = f1v + fms[t];
        mhs[idx] = fmaxf(sv, 0.2f * sv);
    }

    const int cg = tid & 15, tg = tid >> 4;
    u64 acc[NT][3];
    #pragma unroll
    for (int i = 0; i < NT; i++)
        #pragma unroll
        for (int j = 0; j < 3; j++) acc[i][j] = 0ull;

    const int* adjrow = support + (((size_t)b * SS + s) * NN + n0) * NN;
    const float* whbase = &g_wh[s][b][0];
    const float* f2base = &g_f2[s][b][0];

    for (int chunk = 0; chunk < NCHUNK; chunk++) {
        const int m0 = chunk * MT;
        __syncthreads();   // prior step2 done with whs/ws2

        if (tid < NT * MT) {
            int nn = tid / MT, mm = tid % MT;
            masks[tid] = (adjrow[nn * NN + m0 + mm] > 0) ? 1.f : 0.f;
        }
        if (tid < MT * TT) {
            f2c[tid] = f2base[m0 * TT + tid];
        }
        {
            const float4* src = (const float4*)(whbase + (size_t)m0 * TT * CC);
            float4* dst = (float4*)whs;
            for (int i = tid; i < MT * TT * CC / 4; i += 256) dst[i] = src[i];
        }
        __syncthreads();

        // step 1: weights (duplicated pair store) + partial Z
        #pragma unroll
        for (int p = 0; p < 2; p++) {
            int idx = tid + 256 * p;
            if (idx < TT * NT) {
                int t = idx >> 3, nn = idx & 7;
                float f1v = f1s[idx], mhv = mhs[idx], z = 0.f;
                #pragma unroll
                for (int m = 0; m < MT; m++) {
                    float sv = f1v + f2c[m * TT + t];
                    float e = fmaxf(sv, 0.2f * sv);
                    float w = masks[nn * MT + m] * __expf(e - mhv);
                    *(float2*)&ws2[(m * TT + t) * (NT * 2) + nn * 2] = make_float2(w, w);
                    z += w;
                }
                zs[idx] += z;
            }
        }
        __syncthreads();

        // step 2: acc[nn][j] += (w,w) * whv[j]  -- packed f32x2
        #pragma unroll
        for (int m = 0; m < MT; m++) {
            u64 whv[3];
            #pragma unroll
            for (int j = 0; j < 3; j++) {
                int t = 3 * tg + j;
                whv[j] = *(const u64*)&whs[(m * TT + t) * CC + 2 * cg];
            }
            #pragma unroll
            for (int j = 0; j < 3; j++) {
                int t = 3 * tg + j;
                const longlong2* wp = (const longlong2*)&ws2[(m * TT + t) * (NT * 2)];
                longlong2 q0 = wp[0], q1 = wp[1], q2 = wp[2], q3 = wp[3];
                acc[0][j] = ffma2((u64)q0.x, whv[j], acc[0][j]);
                acc[1][j] = ffma2((u64)q0.y, whv[j], acc[1][j]);
                acc[2][j] = ffma2((u64)q1.x, whv[j], acc[2][j]);
                acc[3][j] = ffma2((u64)q1.y, whv[j], acc[3][j]);
                acc[4][j] = ffma2((u64)q2.x, whv[j], acc[4][j]);
                acc[5][j] = ffma2((u64)q2.y, whv[j], acc[5][j]);
                acc[6][j] = ffma2((u64)q3.x, whv[j], acc[6][j]);
                acc[7][j] = ffma2((u64)q3.y, whv[j], acc[7][j]);
            }
        }
    }

    // finalize
    const int slot = 2 * s + hop;
    float* yp = &g_y[slot][b][0];
    #pragma unroll
    for (int nn = 0; nn < NT; nn++) {
        #pragma unroll
        for (int j = 0; j < 3; j++) {
            int t = 3 * tg + j;
            float z = fmaxf(zs[t * NT + nn], 1e-30f);
            float2 hv = unpack2(acc[nn][j]);
            float h0 = __fdividef(hv.x, z);
            float h1 = __fdividef(hv.y, z);
            float y0, y1;
            if (hop == 0) {
                y0 = (h0 > 0.f) ? h0 : (__expf(h0) - 1.f);
                y1 = (h1 > 0.f) ? h1 : (__expf(h1) - 1.f);
            } else {
                y0 = fmaxf(h0, 0.f);
                y1 = fmaxf(h1, 0.f);
            }
            *(float2*)&yp[(size_t)((n0 + nn) * TT + t) * CC + 2 * cg] = make_float2(y0, y1);
        }
    }
}

// ---------------------------------------------------------------------------
// Final concat + 1x1 conv. grid (NN, BB), block 192.
// ---------------------------------------------------------------------------
__global__ __launch_bounds__(192) void mlp_kernel(
    const float* __restrict__ x,
    const float* __restrict__ mw,
    const float* __restrict__ mb,
    float* __restrict__ out)
{
    const int n = blockIdx.x, b = blockIdx.y;
    const int tid = threadIdx.x;
    __shared__ float hb[TT * 32];
    __shared__ float wb[64 * 36];

    const int og = tid % 16, tg = tid / 16;
    float acc[4][4];
    #pragma unroll
    for (int i = 0; i < 4; i++)
        #pragma unroll
        for (int j = 0; j < 4; j++) acc[i][j] = 0.f;

    for (int blk = 0; blk < 7; blk++) {
        __syncthreads();
        if (blk == 0) {
            for (int idx = tid; idx < TT * 32; idx += 192) {
                int f = idx / TT, t = idx % TT;
                hb[t * 32 + f] = x[((size_t)(b * FF + f) * NN + n) * TT + t];
            }
        } else {
            const float* src = &g_y[blk - 1][b][(size_t)n * TT * CC];
            for (int idx = tid; idx < TT * 32; idx += 192) hb[idx] = src[idx];
        }
        for (int idx = tid; idx < 64 * 32; idx += 192) {
            int o = idx / 32, c = idx % 32;
            wb[o * 36 + c] = mw[o * 224 + blk * 32 + c];
        }
        __syncthreads();

        #pragma unroll
        for (int cc = 0; cc < 32; cc += 4) {
            float4 hv[4], wv[4];
            #pragma unroll
            for (int j = 0; j < 4; j++) hv[j] = *(const float4*)&hb[(tg * 4 + j) * 32 + cc];
            #pragma unroll
            for (int i = 0; i < 4; i++) wv[i] = *(const float4*)&wb[(og + 16 * i) * 36 + cc];
            #pragma unroll
            for (int i = 0; i < 4; i++)
                #pragma unroll
                for (int j = 0; j < 4; j++)
                    acc[i][j] += wv[i].x * hv[j].x + wv[i].y * hv[j].y
                               + wv[i].z * hv[j].z + wv[i].w * hv[j].w;
        }
    }

    #pragma unroll
    for (int i = 0; i < 4; i++) {
        int o = og + 16 * i;
        float bias = mb[o];
        float4 r = make_float4(acc[i][0] + bias, acc[i][1] + bias,
                               acc[i][2] + bias, acc[i][3] + bias);
        *(float4*)&out[((size_t)(b * 64 + o) * NN + n) * TT + tg * 4] = r;
    }
}

// ---------------------------------------------------------------------------
extern "C" void kernel_launch(void* const* d_in, const int* in_sizes, int n_in,
                              void* d_out, int out_size)
{
    const float* x       = (const float*)d_in[0];
    const int*   support = (const int*)  d_in[1];
    const float* W1      = (const float*)d_in[2];
    const float* a1      = (const float*)d_in[3];
    const float* WK      = (const float*)d_in[4];
    const float* aK      = (const float*)d_in[5];
    const float* mw      = (const float*)d_in[6];
    const float* mb      = (const float*)d_in[7];
    float* out = (float*)d_out;

    dim3 gwh(NTFLAT / 128, BB, SS);
    dim3 gfm(BB, SS);
    dim3 gagg(NN / NT, BB, SS);
    dim3 gmlp(NN, BB);

    wh_kernel<<<gwh, 256>>>(x, W1, a1, 0);
    f2max_kernel<<<gfm, 64>>>();
    agg_kernel<<<gagg, 256>>>(support, 0);

    wh_kernel<<<gwh, 256>>>(x, WK, aK, 1);
    f2max_kernel<<<gfm, 64>>>();
    agg_kernel<<<gagg, 256>>>(support, 1);

    mlp_kernel<<<gmlp, 192>>>(x, mw, mb, out);
}

// round 5
// speedup vs baseline: 1.4342x; 1.4342x over previous
#include <cuda_runtime.h>
#include <cuda_bf16.h>

#define BB 16
#define FF 32
#define CC 32
#define NN 200
#define TT 48
#define SS 3
#define NT 8
#define MT 4
#define NCHUNK (NN / MT)       // 50
#define NTFLAT (NN * TT)       // 9600

// ---- cp.async helpers ----
__device__ __forceinline__ unsigned smem_u32(const void* p) {
    return (unsigned)__cvta_generic_to_shared(p);
}
#define CPA16(d, s) asm volatile("cp.async.cg.shared.global [%0], [%1], 16;" :: "r"(d), "l"(s))
#define CPC()       asm volatile("cp.async.commit_group;")
#define CPW0()      asm volatile("cp.async.wait_group 0;" ::: "memory")

// Scratch (device globals)
__device__ float g_wh[SS][BB][NTFLAT * CC];   // [(n,t)][c]
__device__ float g_f1[SS][BB][NTFLAT];
__device__ float g_f2[SS][BB][NTFLAT];
__device__ float g_f2max[SS][BB][TT];
__device__ float g_y[6][BB][NTFLAT * CC];     // slot = 2*s + hop

// ---------------------------------------------------------------------------
// Wh + f1/f2. GEMM M=9600 x K=32 x N=32 per (s,b). grid (75, BB, SS), 256 thr.
// ---------------------------------------------------------------------------
__global__ __launch_bounds__(256) void wh_kernel(
    const float* __restrict__ xin,
    const float* __restrict__ Wb,
    const float* __restrict__ ab,
    int layout)
{
    const int b = blockIdx.y, s = blockIdx.z;
    const int base = blockIdx.x * 128;
    const int tid = threadIdx.x;

    __shared__ float xs[128 * 33];
    __shared__ float Ws[FF * CC];
    __shared__ float as_[2 * CC];

    if (layout == 0) {
        const float* src = xin + (size_t)b * FF * NTFLAT + base;
        #pragma unroll
        for (int k = 0; k < 4; k++) {
            int idx4 = tid + 256 * k;
            int f = idx4 >> 5, r4 = (idx4 & 31) * 4;
            float4 v = *(const float4*)(src + (size_t)f * NTFLAT + r4);
            xs[(r4 + 0) * 33 + f] = v.x;
            xs[(r4 + 1) * 33 + f] = v.y;
            xs[(r4 + 2) * 33 + f] = v.z;
            xs[(r4 + 3) * 33 + f] = v.w;
        }
    } else {
        const float* src = &g_y[2 * s][b][(size_t)base * CC];
        #pragma unroll
        for (int k = 0; k < 4; k++) {
            int idx4 = tid + 256 * k;
            int row = idx4 >> 3, q = (idx4 & 7) * 4;
            float4 v = *(const float4*)(src + idx4 * 4);
            xs[row * 33 + q + 0] = v.x;
            xs[row * 33 + q + 1] = v.y;
            xs[row * 33 + q + 2] = v.z;
            xs[row * 33 + q + 3] = v.w;
        }
    }
    {
        const float* W = Wb + (s * BB + b) * (FF * CC);
        if (tid < 256) ((float4*)Ws)[tid] = ((const float4*)W)[tid];
        if (tid < 2 * CC) as_[tid] = ab[(s * BB + b) * (2 * CC) + tid];
    }
    __syncthreads();

    const int cg = tid & 15, rg = tid >> 4;
    const int r0 = rg * 8;
    float acc[8][2];
    #pragma unroll
    for (int i = 0; i < 8; i++) { acc[i][0] = 0.f; acc[i][1] = 0.f; }

    #pragma unroll 8
    for (int f = 0; f < FF; f++) {
        float2 wv = *(const float2*)&Ws[f * CC + 2 * cg];
        #pragma unroll
        for (int i = 0; i < 8; i++) {
            float xv = xs[(r0 + i) * 33 + f];
            acc[i][0] += xv * wv.x;
            acc[i][1] += xv * wv.y;
        }
    }

    float* whp = &g_wh[s][b][0];
    #pragma unroll
    for (int i = 0; i < 8; i++)
        *(float2*)&whp[(size_t)(base + r0 + i) * CC + 2 * cg] =
            make_float2(acc[i][0], acc[i][1]);

    float a1l = as_[2 * cg], a1h = as_[2 * cg + 1];
    float a2l = as_[CC + 2 * cg], a2h = as_[CC + 2 * cg + 1];
    #pragma unroll
    for (int i = 0; i < 8; i++) {
        float p1 = acc[i][0] * a1l + acc[i][1] * a1h;
        float p2 = acc[i][0] * a2l + acc[i][1] * a2h;
        #pragma unroll
        for (int off = 8; off >= 1; off >>= 1) {
            p1 += __shfl_xor_sync(0xffffffffu, p1, off);
            p2 += __shfl_xor_sync(0xffffffffu, p2, off);
        }
        if (cg == 0) {
            g_f1[s][b][base + r0 + i] = p1;
            g_f2[s][b][base + r0 + i] = p2;
        }
    }
}

// ---------------------------------------------------------------------------
__global__ void f2max_kernel()
{
    const int b = blockIdx.x, s = blockIdx.y, t = threadIdx.x;
    if (t < TT) {
        float m = -1e30f;
        for (int n = 0; n < NN; n++) m = fmaxf(m, g_f2[s][b][n * TT + t]);
        g_f2max[s][b][t] = m;
    }
}

// ---------------------------------------------------------------------------
// Attention-aggregation: R2 compute + cp.async double-buffered prefetch.
// grid (25, BB, SS), block 256. cg=tid&15 (c-pair), tg=tid>>4 (3 t's).
// ---------------------------------------------------------------------------
__global__ __launch_bounds__(256) void agg_kernel(const int* __restrict__ support, int hop)
{
    const int nt = blockIdx.x, b = blockIdx.y, s = blockIdx.z;
    const int n0 = nt * NT;
    const int tid = threadIdx.x;

    __shared__ __align__(16) float whs[2][MT * TT * CC];   // 2 x 24576 B
    __shared__ __align__(16) float ws_[MT * TT * NT];      // [m][t][nn] 6144 B
    __shared__ __align__(16) float f2c[2][MT * TT];
    __shared__ __align__(16) int   adjs[2][NT * MT];       // [nn][m]
    __shared__ float f1s[TT * NT];
    __shared__ float mhs[TT * NT];
    __shared__ float zs [TT * NT];
    __shared__ float fms[TT];

    const int* adjrow = support + (((size_t)b * SS + s) * NN + n0) * NN;
    const float* whbase = &g_wh[s][b][0];
    const float* f2base = &g_f2[s][b][0];

    // ---- prefetch chunk k into buffer bf ----
    auto prefetch = [&](int k, int bf) {
        const int m0 = k * MT;
        {
            const float4* src = (const float4*)(whbase + (size_t)m0 * TT * CC);
            unsigned dst = smem_u32(&whs[bf][0]);
            #pragma unroll
            for (int r = 0; r < 6; r++) {
                int i = tid + 256 * r;           // i < 1536
                CPA16(dst + 16 * i, src + i);
            }
        }
        if (tid < MT * TT / 4) {                  // 48 threads
            CPA16(smem_u32(&f2c[bf][tid * 4]), f2base + m0 * TT + tid * 4);
        }
        if (tid < NT) {                           // 8 threads, 16B each
            CPA16(smem_u32(&adjs[bf][tid * MT]), adjrow + tid * NN + m0);
        }
        CPC();
    };

    prefetch(0, 0);

    if (tid < TT) fms[tid] = g_f2max[s][b][tid];
    __syncthreads();
    for (int idx = tid; idx < TT * NT; idx += 256) {
        int t = idx >> 3, nn = idx & 7;
        float f1v = g_f1[s][b][(n0 + nn) * TT + t];
        f1s[idx] = f1v;
        zs[idx] = 0.f;
        float sv = f1v + fms[t];
        mhs[idx] = fmaxf(sv, 0.2f * sv);
    }

    const int cg = tid & 15, tg = tid >> 4;
    float acc[NT][6];
    #pragma unroll
    for (int i = 0; i < NT; i++)
        #pragma unroll
        for (int j = 0; j < 6; j++) acc[i][j] = 0.f;

    for (int k = 0; k < NCHUNK; k++) {
        const int bf = k & 1;
        CPW0();
        __syncthreads();                       // chunk k visible; ws_ free
        if (k + 1 < NCHUNK) prefetch(k + 1, bf ^ 1);

        // step 1: weights + partial Z. tasks idx = t*8+nn (384 tasks)
        #pragma unroll
        for (int p = 0; p < 2; p++) {
            int idx = tid + 256 * p;
            if (idx < TT * NT) {
                int t = idx >> 3, nn = idx & 7;
                float f1v = f1s[idx], mhv = mhs[idx], z = 0.f;
                #pragma unroll
                for (int m = 0; m < MT; m++) {
                    float sv = f1v + f2c[bf][m * TT + t];
                    float e = fmaxf(sv, 0.2f * sv);
                    float w = (adjs[bf][nn * MT + m] > 0) ? __expf(e - mhv) : 0.f;
                    ws_[(m * TT + t) * NT + nn] = w;
                    z += w;
                }
                zs[idx] += z;
            }
        }
        __syncthreads();

        // step 2: acc[nn][2j+q] += ws_[m][t][nn] * whs[m][t][2cg+q]
        #pragma unroll
        for (int m = 0; m < MT; m++) {
            float2 whv[3];
            float4 wa[3], wb[3];
            #pragma unroll
            for (int j = 0; j < 3; j++) {
                int t = 3 * tg + j;
                whv[j] = *(const float2*)&whs[bf][(m * TT + t) * CC + 2 * cg];
                const float4* wp = (const float4*)&ws_[(m * TT + t) * NT];
                wa[j] = wp[0];
                wb[j] = wp[1];
            }
            #pragma unroll
            for (int j = 0; j < 3; j++) {
                acc[0][2*j]   += wa[j].x * whv[j].x;  acc[0][2*j+1] += wa[j].x * whv[j].y;
                acc[1][2*j]   += wa[j].y * whv[j].x;  acc[1][2*j+1] += wa[j].y * whv[j].y;
                acc[2][2*j]   += wa[j].z * whv[j].x;  acc[2][2*j+1] += wa[j].z * whv[j].y;
                acc[3][2*j]   += wa[j].w * whv[j].x;  acc[3][2*j+1] += wa[j].w * whv[j].y;
                acc[4][2*j]   += wb[j].x * whv[j].x;  acc[4][2*j+1] += wb[j].x * whv[j].y;
                acc[5][2*j]   += wb[j].y * whv[j].x;  acc[5][2*j+1] += wb[j].y * whv[j].y;
                acc[6][2*j]   += wb[j].z * whv[j].x;  acc[6][2*j+1] += wb[j].z * whv[j].y;
                acc[7][2*j]   += wb[j].w * whv[j].x;  acc[7][2*j+1] += wb[j].w * whv[j].y;
            }
        }
    }

    // finalize
    const int slot = 2 * s + hop;
    float* yp = &g_y[slot][b][0];
    #pragma unroll
    for (int nn = 0; nn < NT; nn++) {
        #pragma unroll
        for (int j = 0; j < 3; j++) {
            int t = 3 * tg + j;
            float z = fmaxf(zs[t * NT + nn], 1e-30f);
            float h0 = __fdividef(acc[nn][2*j],   z);
            float h1 = __fdividef(acc[nn][2*j+1], z);
            float y0, y1;
            if (hop == 0) {
                y0 = (h0 > 0.f) ? h0 : (__expf(h0) - 1.f);
                y1 = (h1 > 0.f) ? h1 : (__expf(h1) - 1.f);
            } else {
                y0 = fmaxf(h0, 0.f);
                y1 = fmaxf(h1, 0.f);
            }
            *(float2*)&yp[(size_t)((n0 + nn) * TT + t) * CC + 2 * cg] = make_float2(y0, y1);
        }
    }
}

// ---------------------------------------------------------------------------
// Final concat + 1x1 conv. grid (NN, BB), block 192.
// ---------------------------------------------------------------------------
__global__ __launch_bounds__(192) void mlp_kernel(
    const float* __restrict__ x,
    const float* __restrict__ mw,
    const float* __restrict__ mb,
    float* __restrict__ out)
{
    const int n = blockIdx.x, b = blockIdx.y;
    const int tid = threadIdx.x;
    __shared__ float hb[TT * 32];
    __shared__ float wb[64 * 36];

    const int og = tid % 16, tg = tid / 16;
    float acc[4][4];
    #pragma unroll
    for (int i = 0; i < 4; i++)
        #pragma unroll
        for (int j = 0; j < 4; j++) acc[i][j] = 0.f;

    for (int blk = 0; blk < 7; blk++) {
        __syncthreads();
        if (blk == 0) {
            for (int idx = tid; idx < TT * 32; idx += 192) {
                int f = idx / TT, t = idx % TT;
                hb[t * 32 + f] = x[((size_t)(b * FF + f) * NN + n) * TT + t];
            }
        } else {
            const float* src = &g_y[blk - 1][b][(size_t)n * TT * CC];
            for (int idx = tid; idx < TT * 32; idx += 192) hb[idx] = src[idx];
        }
        for (int idx = tid; idx < 64 * 32; idx += 192) {
            int o = idx / 32, c = idx % 32;
            wb[o * 36 + c] = mw[o * 224 + blk * 32 + c];
        }
        __syncthreads();

        #pragma unroll
        for (int cc = 0; cc < 32; cc += 4) {
            float4 hv[4], wv[4];
            #pragma unroll
            for (int j = 0; j < 4; j++) hv[j] = *(const float4*)&hb[(tg * 4 + j) * 32 + cc];
            #pragma unroll
            for (int i = 0; i < 4; i++) wv[i] = *(const float4*)&wb[(og + 16 * i) * 36 + cc];
            #pragma unroll
            for (int i = 0; i < 4; i++)
                #pragma unroll
                for (int j = 0; j < 4; j++)
                    acc[i][j] += wv[i].x * hv[j].x + wv[i].y * hv[j].y
                               + wv[i].z * hv[j].z + wv[i].w * hv[j].w;
        }
    }

    #pragma unroll
    for (int i = 0; i < 4; i++) {
        int o = og + 16 * i;
        float bias = mb[o];
        float4 r = make_float4(acc[i][0] + bias, acc[i][1] + bias,
                               acc[i][2] + bias, acc[i][3] + bias);
        *(float4*)&out[((size_t)(b * 64 + o) * NN + n) * TT + tg * 4] = r;
    }
}

// ---------------------------------------------------------------------------
extern "C" void kernel_launch(void* const* d_in, const int* in_sizes, int n_in,
                              void* d_out, int out_size)
{
    const float* x       = (const float*)d_in[0];
    const int*   support = (const int*)  d_in[1];
    const float* W1      = (const float*)d_in[2];
    const float* a1      = (const float*)d_in[3];
    const float* WK      = (const float*)d_in[4];
    const float* aK      = (const float*)d_in[5];
    const float* mw      = (const float*)d_in[6];
    const float* mb      = (const float*)d_in[7];
    float* out = (float*)d_out;

    dim3 gwh(NTFLAT / 128, BB, SS);
    dim3 gfm(BB, SS);
    dim3 gagg(NN / NT, BB, SS);
    dim3 gmlp(NN, BB);

    wh_kernel<<<gwh, 256>>>(x, W1, a1, 0);
    f2max_kernel<<<gfm, 64>>>();
    agg_kernel<<<gagg, 256>>>(support, 0);

    wh_kernel<<<gwh, 256>>>(x, WK, aK, 1);
    f2max_kernel<<<gfm, 64>>>();
    agg_kernel<<<gagg, 256>>>(support, 1);

    mlp_kernel<<<gmlp, 192>>>(x, mw, mb, out);
}

// round 6
// speedup vs baseline: 1.5605x; 1.0881x over previous
#include <cuda_runtime.h>
#include <cuda_bf16.h>

#define BB 16
#define FF 32
#define CC 32
#define NN 200
#define TT 48
#define SS 3
#define MC 32               // m-chunk in agg
#define NCH 7               // 6 full chunks + 1 partial (8)
#define NP 224              // padded N for t-major buffers
#define NTFLAT (NN * TT)    // 9600

// ---- cp.async helpers ----
__device__ __forceinline__ unsigned smem_u32(const void* p) {
    return (unsigned)__cvta_generic_to_shared(p);
}
#define CPA16(d, s) asm volatile("cp.async.cg.shared.global [%0], [%1], 16;" :: "r"(d), "l"(s))
#define CPC()       asm volatile("cp.async.commit_group;")
#define CPW0()      asm volatile("cp.async.wait_group 0;" ::: "memory")

// Scratch (device globals)
__device__ float g_wh[SS][BB][NTFLAT * CC];       // [(n,t)][c]
__device__ float g_f1t[SS][BB][TT * NP];          // [t][n]
__device__ float g_f2t[SS][BB][TT * NP];          // [t][n]
__device__ float g_f2max[SS][BB][TT];
__device__ unsigned g_adjb[BB * SS][NCH][NP];     // bitmask, word-major
__device__ float g_y[6][BB][NTFLAT * CC];         // slot = 2*s + hop

// ---------------------------------------------------------------------------
// Adjacency bit-pack: grid 48 (=b*3+s), 256 threads. Once per launch.
// ---------------------------------------------------------------------------
__global__ void adjbit_kernel(const int* __restrict__ support)
{
    const int bs = blockIdx.x;            // b*SS+s
    const int warp = threadIdx.x >> 5, lane = threadIdx.x & 31;
    const int* adj = support + (size_t)bs * NN * NN;
    for (int pid = warp; pid < NN * NCH; pid += 8) {
        int n = pid / NCH, wi = pid % NCH;
        int mm = wi * 32 + lane;
        int v = (mm < NN) ? (adj[n * NN + mm] > 0) : 0;
        unsigned word = __ballot_sync(0xffffffffu, v);
        if (lane == 0) g_adjb[bs][wi][n] = word;
    }
    // zero the padded tail n in [NN, NP)
    if (threadIdx.x < NP - NN) {
        for (int wi = 0; wi < NCH; wi++) g_adjb[bs][wi][NN + threadIdx.x] = 0u;
    }
}

// ---------------------------------------------------------------------------
// Wh + f1/f2 (t-major outputs). grid (75, BB, SS), 256 threads.
// ---------------------------------------------------------------------------
__global__ __launch_bounds__(256) void wh_kernel(
    const float* __restrict__ xin,
    const float* __restrict__ Wb,
    const float* __restrict__ ab,
    int layout)
{
    const int b = blockIdx.y, s = blockIdx.z;
    const int base = blockIdx.x * 128;
    const int tid = threadIdx.x;

    __shared__ float xs[128 * 33];
    __shared__ float Ws[FF * CC];
    __shared__ float as_[2 * CC];

    if (layout == 0) {
        const float* src = xin + (size_t)b * FF * NTFLAT + base;
        #pragma unroll
        for (int k = 0; k < 4; k++) {
            int idx4 = tid + 256 * k;
            int f = idx4 >> 5, r4 = (idx4 & 31) * 4;
            float4 v = *(const float4*)(src + (size_t)f * NTFLAT + r4);
            xs[(r4 + 0) * 33 + f] = v.x;
            xs[(r4 + 1) * 33 + f] = v.y;
            xs[(r4 + 2) * 33 + f] = v.z;
            xs[(r4 + 3) * 33 + f] = v.w;
        }
    } else {
        const float* src = &g_y[2 * s][b][(size_t)base * CC];
        #pragma unroll
        for (int k = 0; k < 4; k++) {
            int idx4 = tid + 256 * k;
            int row = idx4 >> 3, q = (idx4 & 7) * 4;
            float4 v = *(const float4*)(src + idx4 * 4);
            xs[row * 33 + q + 0] = v.x;
            xs[row * 33 + q + 1] = v.y;
            xs[row * 33 + q + 2] = v.z;
            xs[row * 33 + q + 3] = v.w;
        }
    }
    {
        const float* W = Wb + (s * BB + b) * (FF * CC);
        if (tid < 256) ((float4*)Ws)[tid] = ((const float4*)W)[tid];
        if (tid < 2 * CC) as_[tid] = ab[(s * BB + b) * (2 * CC) + tid];
    }
    __syncthreads();

    const int cg = tid & 15, rg = tid >> 4;
    const int r0 = rg * 8;
    float acc[8][2];
    #pragma unroll
    for (int i = 0; i < 8; i++) { acc[i][0] = 0.f; acc[i][1] = 0.f; }

    #pragma unroll 8
    for (int f = 0; f < FF; f++) {
        float2 wv = *(const float2*)&Ws[f * CC + 2 * cg];
        #pragma unroll
        for (int i = 0; i < 8; i++) {
            float xv = xs[(r0 + i) * 33 + f];
            acc[i][0] += xv * wv.x;
            acc[i][1] += xv * wv.y;
        }
    }

    float* whp = &g_wh[s][b][0];
    #pragma unroll
    for (int i = 0; i < 8; i++)
        *(float2*)&whp[(size_t)(base + r0 + i) * CC + 2 * cg] =
            make_float2(acc[i][0], acc[i][1]);

    float a1l = as_[2 * cg], a1h = as_[2 * cg + 1];
    float a2l = as_[CC + 2 * cg], a2h = as_[CC + 2 * cg + 1];
    #pragma unroll
    for (int i = 0; i < 8; i++) {
        float p1 = acc[i][0] * a1l + acc[i][1] * a1h;
        float p2 = acc[i][0] * a2l + acc[i][1] * a2h;
        #pragma unroll
        for (int off = 8; off >= 1; off >>= 1) {
            p1 += __shfl_xor_sync(0xffffffffu, p1, off);
            p2 += __shfl_xor_sync(0xffffffffu, p2, off);
        }
        if (cg == 0) {
            int row = base + r0 + i;
            int n = row / TT, t = row % TT;
            g_f1t[s][b][t * NP + n] = p1;
            g_f2t[s][b][t * NP + n] = p2;
        }
    }
}

// ---------------------------------------------------------------------------
// f2max over n (reads t-major). grid (BB, SS), block 64.
// ---------------------------------------------------------------------------
__global__ void f2max_kernel()
{
    const int b = blockIdx.x, s = blockIdx.y, t = threadIdx.x;
    if (t < TT) {
        const float* p = &g_f2t[s][b][t * NP];
        float m = -1e30f;
        for (int n = 0; n < NN; n++) m = fmaxf(m, p[n]);
        g_f2max[s][b][t] = m;
    }
}

// ---------------------------------------------------------------------------
// Attention-aggregation, t-major. grid (TT, BB, SS), block 256.
// step1: thread n computes weights for one n row. step2: c=tid&31, ng=tid>>5,
// n = ng + 8k (k<25), acc[25] registers.
// ---------------------------------------------------------------------------
__global__ __launch_bounds__(256) void agg_kernel(int hop)
{
    const int t = blockIdx.x, b = blockIdx.y, s = blockIdx.z;
    const int bs = b * SS + s;
    const int tid = threadIdx.x;

    __shared__ __align__(16) float whs[2][MC * 36];   // [m][c] stride 36, 2x4608B
    __shared__ __align__(16) float wsm[NN * 36];      // [n][m] stride 36, 28800B
    __shared__ __align__(16) float f2c[2][MC];
    __shared__ __align__(16) unsigned adjw[2][NP];
    __shared__ float zsm[NN];

    const float* whbase = &g_wh[s][b][0];
    const float* f1tp = &g_f1t[s][b][t * NP];
    const float* f2tp = &g_f2t[s][b][t * NP];
    const float fms = g_f2max[s][b][t];

    auto prefetch = [&](int k, int bf) {
        const int m0 = k * MC;
        {
            int m = tid >> 3, q = tid & 7;
            int mrow = min(m0 + m, NN - 1);
            CPA16(smem_u32(&whs[bf][m * 36 + q * 4]),
                  whbase + ((size_t)mrow * TT + t) * CC + q * 4);
        }
        if (tid < MC / 4)
            CPA16(smem_u32(&f2c[bf][tid * 4]), f2tp + m0 + tid * 4);
        if (tid < NP / 4)
            CPA16(smem_u32(&adjw[bf][tid * 4]), &g_adjb[bs][k][tid * 4]);
        CPC();
    };

    prefetch(0, 0);

    // per-thread step1 params
    float f1v = 0.f, mhv = 0.f, z = 0.f;
    if (tid < NN) {
        f1v = f1tp[tid];
        float sv = f1v + fms;
        mhv = fmaxf(sv, 0.2f * sv);
    }

    const int c = tid & 31, ng = tid >> 5;
    float acc[25];
    #pragma unroll
    for (int k = 0; k < 25; k++) acc[k] = 0.f;

    for (int k = 0; k < NCH; k++) {
        const int bf = k & 1;
        const int mc = (k == NCH - 1) ? (NN - (NCH - 1) * MC) : MC;   // 8 or 32
        CPW0();
        __syncthreads();
        if (k + 1 < NCH) prefetch(k + 1, bf ^ 1);

        // step 1: thread n = tid
        if (tid < NN) {
            unsigned aw = adjw[bf][tid];
            if (mc == MC) {
                #pragma unroll
                for (int mg = 0; mg < MC / 4; mg++) {
                    float4 wq;
                    float* wp = &wq.x;
                    #pragma unroll
                    for (int j = 0; j < 4; j++) {
                        int m = mg * 4 + j;
                        float sv = f1v + f2c[bf][m];
                        float e = fmaxf(sv, 0.2f * sv);
                        float w = ((aw >> m) & 1u) ? __expf(e - mhv) : 0.f;
                        wp[j] = w;
                        z += w;
                    }
                    *(float4*)&wsm[tid * 36 + mg * 4] = wq;
                }
            } else {
                #pragma unroll
                for (int mg = 0; mg < 2; mg++) {
                    float4 wq;
                    float* wp = &wq.x;
                    #pragma unroll
                    for (int j = 0; j < 4; j++) {
                        int m = mg * 4 + j;
                        float sv = f1v + f2c[bf][m];
                        float e = fmaxf(sv, 0.2f * sv);
                        float w = ((aw >> m) & 1u) ? __expf(e - mhv) : 0.f;
                        wp[j] = w;
                        z += w;
                    }
                    *(float4*)&wsm[tid * 36 + mg * 4] = wq;
                }
            }
        }
        __syncthreads();

        // step 2
        const int groups = mc / 4;
        for (int g = 0; g < groups; g++) {
            float wh0 = whs[bf][(4 * g + 0) * 36 + c];
            float wh1 = whs[bf][(4 * g + 1) * 36 + c];
            float wh2 = whs[bf][(4 * g + 2) * 36 + c];
            float wh3 = whs[bf][(4 * g + 3) * 36 + c];
            #pragma unroll
            for (int kk = 0; kk < 25; kk++) {
                int n = ng + 8 * kk;
                float4 wq = *(const float4*)&wsm[n * 36 + 4 * g];
                acc[kk] += wq.x * wh0 + wq.y * wh1 + wq.z * wh2 + wq.w * wh3;
            }
        }
    }

    if (tid < NN) zsm[tid] = z;
    __syncthreads();

    const int slot = 2 * s + hop;
    float* yp = &g_y[slot][b][0];
    #pragma unroll
    for (int kk = 0; kk < 25; kk++) {
        int n = ng + 8 * kk;
        float zv = fmaxf(zsm[n], 1e-30f);
        float h = __fdividef(acc[kk], zv);
        float y;
        if (hop == 0) y = (h > 0.f) ? h : (__expf(h) - 1.f);
        else          y = fmaxf(h, 0.f);
        yp[(size_t)(n * TT + t) * CC + c] = y;
    }
}

// ---------------------------------------------------------------------------
// Final concat + 1x1 conv. grid (NN, BB), block 192.
// ---------------------------------------------------------------------------
__global__ __launch_bounds__(192) void mlp_kernel(
    const float* __restrict__ x,
    const float* __restrict__ mw,
    const float* __restrict__ mb,
    float* __restrict__ out)
{
    const int n = blockIdx.x, b = blockIdx.y;
    const int tid = threadIdx.x;
    __shared__ float hb[TT * 32];
    __shared__ float wb[64 * 36];

    const int og = tid % 16, tg = tid / 16;
    float acc[4][4];
    #pragma unroll
    for (int i = 0; i < 4; i++)
        #pragma unroll
        for (int j = 0; j < 4; j++) acc[i][j] = 0.f;

    for (int blk = 0; blk < 7; blk++) {
        __syncthreads();
        if (blk == 0) {
            for (int idx = tid; idx < TT * 32; idx += 192) {
                int f = idx / TT, t = idx % TT;
                hb[t * 32 + f] = x[((size_t)(b * FF + f) * NN + n) * TT + t];
            }
        } else {
            const float* src = &g_y[blk - 1][b][(size_t)n * TT * CC];
            for (int idx = tid; idx < TT * 32; idx += 192) hb[idx] = src[idx];
        }
        for (int idx = tid; idx < 64 * 32; idx += 192) {
            int o = idx / 32, c = idx % 32;
            wb[o * 36 + c] = mw[o * 224 + blk * 32 + c];
        }
        __syncthreads();

        #pragma unroll
        for (int cc = 0; cc < 32; cc += 4) {
            float4 hv[4], wv[4];
            #pragma unroll
            for (int j = 0; j < 4; j++) hv[j] = *(const float4*)&hb[(tg * 4 + j) * 32 + cc];
            #pragma unroll
            for (int i = 0; i < 4; i++) wv[i] = *(const float4*)&wb[(og + 16 * i) * 36 + cc];
            #pragma unroll
            for (int i = 0; i < 4; i++)
                #pragma unroll
                for (int j = 0; j < 4; j++)
                    acc[i][j] += wv[i].x * hv[j].x + wv[i].y * hv[j].y
                               + wv[i].z * hv[j].z + wv[i].w * hv[j].w;
        }
    }

    #pragma unroll
    for (int i = 0; i < 4; i++) {
        int o = og + 16 * i;
        float bias = mb[o];
        float4 r = make_float4(acc[i][0] + bias, acc[i][1] + bias,
                               acc[i][2] + bias, acc[i][3] + bias);
        *(float4*)&out[((size_t)(b * 64 + o) * NN + n) * TT + tg * 4] = r;
    }
}

// ---------------------------------------------------------------------------
extern "C" void kernel_launch(void* const* d_in, const int* in_sizes, int n_in,
                              void* d_out, int out_size)
{
    const float* x       = (const float*)d_in[0];
    const int*   support = (const int*)  d_in[1];
    const float* W1      = (const float*)d_in[2];
    const float* a1      = (const float*)d_in[3];
    const float* WK      = (const float*)d_in[4];
    const float* aK      = (const float*)d_in[5];
    const float* mw      = (const float*)d_in[6];
    const float* mb      = (const float*)d_in[7];
    float* out = (float*)d_out;

    dim3 gwh(NTFLAT / 128, BB, SS);
    dim3 gfm(BB, SS);
    dim3 gagg(TT, BB, SS);
    dim3 gmlp(NN, BB);

    adjbit_kernel<<<BB * SS, 256>>>(support);

    wh_kernel<<<gwh, 256>>>(x, W1, a1, 0);
    f2max_kernel<<<gfm, 64>>>();
    agg_kernel<<<gagg, 256>>>(0);

    wh_kernel<<<gwh, 256>>>(x, WK, aK, 1);
    f2max_kernel<<<gfm, 64>>>();
    agg_kernel<<<gagg, 256>>>(1);

    mlp_kernel<<<gmlp, 192>>>(x, mw, mb, out);
}